// round 14
// baseline (speedup 1.0000x reference)
#include <cuda_runtime.h>
#include <cuda_fp16.h>

#define BB 8
#define CC 64
#define HH 256
#define WW 448
#define HW (HH * WW)            // 114688
#define CHW (CC * HW)           // 7340032

// 14 MB fp16 NHWC scratch for one batch (internal only).
__device__ __align__(256) __half g_nhwc[HW * CC];

__device__ __forceinline__ unsigned h2_bits(__half2 h)
{
    unsigned u;
    *(__half2*)&u = h;
    return u;
}
__device__ __forceinline__ __half2 bits_h2(unsigned u)
{
    return *(__half2*)&u;
}

// swizzled staging index: layout [c][p], stride 128, p XOR 4*(c/4).
#define S2IDX(c, p) ((c) * 128 + ((((p) ^ (((c) >> 2) << 2))) & 127))

// ---------------------------------------------------------------------------
// Transpose: NCHW fp32 -> NHWC fp16, 128px x 64ch tile, MLP 8.
// ---------------------------------------------------------------------------
__global__ __launch_bounds__(256)
void transpose_kernel(const float* __restrict__ in)   // in = input1 + b*CHW
{
    __shared__ float smf[128 * 67];

    const int tid = threadIdx.x;
    const int pbase = blockIdx.x * 128;

    const float4* __restrict__ in4 = (const float4*)in;

    {
        const int pq = tid & 31;          // float4 column (0..31 -> 128 px)
        const int c0 = tid >> 5;          // 0..7
        float4 v[8];
        #pragma unroll
        for (int i = 0; i < 8; i++) {     // 8 independent LDG.128
            const int c = c0 + 8 * i;
            v[i] = __ldcs(in4 + (size_t)c * (HW / 4) + (pbase >> 2) + pq);
        }
        #pragma unroll
        for (int i = 0; i < 8; i++) {
            const int c = c0 + 8 * i;
            const int pl = 4 * pq;
            smf[(pl + 0) * 67 + c] = v[i].x;
            smf[(pl + 1) * 67 + c] = v[i].y;
            smf[(pl + 2) * 67 + c] = v[i].z;
            smf[(pl + 3) * 67 + c] = v[i].w;
        }
    }
    __syncthreads();
    {
        uint2* __restrict__ dst2 = (uint2*)g_nhwc;    // 16 uint2 per pixel
        const int t  = tid & 15;          // channel quad
        const int p0 = tid >> 4;          // 0..15
        #pragma unroll
        for (int i = 0; i < 8; i++) {
            const int p = p0 + 16 * i;
            const float* r = &smf[p * 67 + 4 * t];
            uint2 v;
            v.x = h2_bits(__floats2half2_rn(r[0], r[1]));
            v.y = h2_bits(__floats2half2_rn(r[2], r[3]));
            dst2[(size_t)(pbase + p) * 16 + t] = v;
        }
    }
}

// ---------------------------------------------------------------------------
// Gather: 512 threads = 128 pixels x 16 quads, 4 pixels/thread (MLP 16).
// ---------------------------------------------------------------------------
__global__ __launch_bounds__(512)
void warp_gather_kernel(const float* __restrict__ flow,  // flow + b*2*HW
                        float* __restrict__ out)         // out + b*CHW
{
    __shared__ uint4 s_wh[128];      // 4x packed half2 weights per pixel
    __shared__ int4  s_o[128];
    __shared__ float s2[64 * 128];   // swizzled [channel][pixel]

    const int tid = threadIdx.x;
    const int pbase = blockIdx.x * 128;

    if (tid < 128) {
        const int p = pbase + tid;
        const int h = p / WW;
        const int w = p - h * WW;

        const float fx = __ldcs(flow + p);
        const float fy = __ldcs(flow + HW + p);

        const float x = (float)w + fx;
        const float y = (float)h + fy;

        const float x0f = floorf(x);
        const float y0f = floorf(y);
        const int x0 = (int)x0f;
        const int y0 = (int)y0f;
        const int x1 = x0 + 1;
        const int y1 = y0 + 1;

        const float wx1 = x - x0f;
        const float wx0 = 1.0f - wx1;
        const float wy1 = y - y0f;
        const float wy0 = 1.0f - wy1;

        const bool vx0 = (x0 >= 0) & (x0 <= WW - 1);
        const bool vx1 = (x1 >= 0) & (x1 <= WW - 1);
        const bool vy0 = (y0 >= 0) & (y0 <= HH - 1);
        const bool vy1 = (y1 >= 0) & (y1 <= HH - 1);

        const float w00 = (vy0 & vx0) ? wy0 * wx0 : 0.0f;
        const float w01 = (vy0 & vx1) ? wy0 * wx1 : 0.0f;
        const float w10 = (vy1 & vx0) ? wy1 * wx0 : 0.0f;
        const float w11 = (vy1 & vx1) ? wy1 * wx1 : 0.0f;

        uint4 wh;
        wh.x = h2_bits(__half2half2(__float2half_rn(w00)));
        wh.y = h2_bits(__half2half2(__float2half_rn(w01)));
        wh.z = h2_bits(__half2half2(__float2half_rn(w10)));
        wh.w = h2_bits(__half2half2(__float2half_rn(w11)));

        const int xc0 = min(max(x0, 0), WW - 1);
        const int xc1 = min(max(x1, 0), WW - 1);
        const int yc0 = min(max(y0, 0), HH - 1);
        const int yc1 = min(max(y1, 0), HH - 1);

        int4 off;   // uint2 index of the pixel's 64-ch fp16 block (16 uint2/px)
        off.x = (yc0 * WW + xc0) * 16;
        off.y = (yc0 * WW + xc1) * 16;
        off.z = (yc1 * WW + xc0) * 16;
        off.w = (yc1 * WW + xc1) * 16;

        s_wh[tid] = wh;
        s_o[tid]  = off;
    }
    __syncthreads();

    const int t = tid & 15;          // channel quad
    const int c0 = 4 * t;
    const uint2* __restrict__ s8 = (const uint2*)g_nhwc;

    // 4 pixels per thread: issue all 16 LDG.64 before consuming any.
    int pxl[4];
    uint4 wh[4];
    int4  off[4];
    #pragma unroll
    for (int q = 0; q < 4; q++) {
        pxl[q] = (tid >> 4) + 32 * q;
        wh[q]  = s_wh[pxl[q]];
        off[q] = s_o[pxl[q]];
    }

    uint2 tp[4][4];
    #pragma unroll
    for (int q = 0; q < 4; q++) {
        tp[q][0] = __ldg(s8 + off[q].x + t);
        tp[q][1] = __ldg(s8 + off[q].y + t);
        tp[q][2] = __ldg(s8 + off[q].z + t);
        tp[q][3] = __ldg(s8 + off[q].w + t);
    }

    #pragma unroll
    for (int q = 0; q < 4; q++) {
        __half2 acc01 = __hmul2(bits_h2(wh[q].x), bits_h2(tp[q][0].x));
        acc01 = __hfma2(bits_h2(wh[q].y), bits_h2(tp[q][1].x), acc01);
        acc01 = __hfma2(bits_h2(wh[q].z), bits_h2(tp[q][2].x), acc01);
        acc01 = __hfma2(bits_h2(wh[q].w), bits_h2(tp[q][3].x), acc01);
        __half2 acc23 = __hmul2(bits_h2(wh[q].x), bits_h2(tp[q][0].y));
        acc23 = __hfma2(bits_h2(wh[q].y), bits_h2(tp[q][1].y), acc23);
        acc23 = __hfma2(bits_h2(wh[q].z), bits_h2(tp[q][2].y), acc23);
        acc23 = __hfma2(bits_h2(wh[q].w), bits_h2(tp[q][3].y), acc23);

        const float2 f01 = __half22float2(acc01);
        const float2 f23 = __half22float2(acc23);

        s2[S2IDX(c0 + 0, pxl[q])] = f01.x;
        s2[S2IDX(c0 + 1, pxl[q])] = f01.y;
        s2[S2IDX(c0 + 2, pxl[q])] = f23.x;
        s2[S2IDX(c0 + 3, pxl[q])] = f23.y;
    }
    __syncthreads();

    // 8192 floats = 2048 float4: 4 iters x 512 threads. Per warp: 32
    // consecutive float4 of one channel = 512B contiguous STG.128.
    float4* __restrict__ out4 = (float4*)out;
    #pragma unroll
    for (int k = 0; k < 4; k++) {
        const int idx = tid + 512 * k;
        const int c  = idx >> 5;         // 0..63
        const int j4 = idx & 31;         // float4 column 0..31
        const float4 v = *(const float4*)&s2[c * 128 + (((4 * j4) ^ (((c) >> 2) << 2)) & 127)];
        __stcs(out4 + (size_t)c * (HW / 4) + (pbase >> 2) + j4, v);
    }
}

extern "C" void kernel_launch(void* const* d_in, const int* in_sizes, int n_in,
                              void* d_out, int out_size)
{
    const float* input1 = (const float*)d_in[0];  // [8,64,256,448] fp32
    const float* input2 = (const float*)d_in[1];  // [8,2,256,448] fp32
    float* out = (float*)d_out;

    const int TBLOCKS = HW / 128;  // 896
    const int GBLOCKS = HW / 128;  // 896

    for (int b = 0; b < BB; b++) {
        transpose_kernel<<<TBLOCKS, 256>>>(input1 + (size_t)b * CHW);
        warp_gather_kernel<<<GBLOCKS, 512>>>(input2 + (size_t)b * 2 * HW,
                                             out + (size_t)b * CHW);
    }
}

// round 16
// speedup vs baseline: 1.1435x; 1.1435x over previous
#include <cuda_runtime.h>
#include <cuda_fp16.h>

#define BB 8
#define CC 64
#define HH 256
#define WW 448
#define HW (HH * WW)            // 114688
#define CHW (CC * HW)           // 7340032

// 14 MB fp16 NHWC scratch for one batch (internal only).
__device__ __align__(256) __half g_nhwc[HW * CC];

__device__ __forceinline__ unsigned h2_bits(__half2 h)
{
    unsigned u;
    *(__half2*)&u = h;
    return u;
}
__device__ __forceinline__ __half2 bits_h2(unsigned u)
{
    return *(__half2*)&u;
}

// swizzled staging index: layout [c][p], stride 64, p XOR 4*(c/4).
#define S2IDX(c, p) ((c) * 64 + ((((p) ^ (((c) >> 2) << 2))) & 63))

// ---------------------------------------------------------------------------
// Transpose: NCHW fp32 -> NHWC fp16, 64px x 64ch tile. (R13 proven version)
// ---------------------------------------------------------------------------
__global__ __launch_bounds__(256)
void transpose_kernel(const float* __restrict__ in)   // in = input1 + b*CHW
{
    __shared__ float smf[64 * 67];

    const int tid = threadIdx.x;
    const int pbase = blockIdx.x * 64;

    const float4* __restrict__ in4 = (const float4*)in;

    {
        const int pq = tid & 15;          // float4 column (0..15 -> 64 px)
        const int c0 = tid >> 4;          // 0..15
        #pragma unroll
        for (int i = 0; i < 4; i++) {
            const int c = c0 + 16 * i;
            const float4 v = __ldcs(in4 + (size_t)c * (HW / 4) + (pbase >> 2) + pq);
            const int pl = 4 * pq;
            smf[(pl + 0) * 67 + c] = v.x;
            smf[(pl + 1) * 67 + c] = v.y;
            smf[(pl + 2) * 67 + c] = v.z;
            smf[(pl + 3) * 67 + c] = v.w;
        }
    }
    __syncthreads();
    {
        uint2* __restrict__ dst2 = (uint2*)g_nhwc;    // 16 uint2 per pixel
        const int t  = tid & 15;          // channel quad
        const int p0 = tid >> 4;          // 0..15
        #pragma unroll
        for (int i = 0; i < 4; i++) {
            const int p = p0 + 16 * i;
            const float* r = &smf[p * 67 + 4 * t];
            uint2 v;
            v.x = h2_bits(__floats2half2_rn(r[0], r[1]));
            v.y = h2_bits(__floats2half2_rn(r[2], r[3]));
            dst2[(size_t)(pbase + p) * 16 + t] = v;
        }
    }
}

// ---------------------------------------------------------------------------
// Gather: 512 threads = 64 pixels x 16 quads, 2 pixels/thread.
// Param phase: ALL threads compute (8x redundant per pixel) so every warp
// issues its own flow loads concurrently -> no serialized prologue barrier.
// Grid is 2D (w-tile, row) -> no integer division.
// ---------------------------------------------------------------------------
__global__ __launch_bounds__(512)
void warp_gather_kernel(const float* __restrict__ flow,  // flow + b*2*HW
                        float* __restrict__ out)         // out + b*CHW
{
    __shared__ uint4 s_wh[64];       // 4x packed half2 weights per pixel
    __shared__ int4  s_o[64];
    __shared__ float s2[64 * 64];    // swizzled [channel][pixel]

    const int tid = threadIdx.x;
    const int h  = blockIdx.y;           // row
    const int w0 = blockIdx.x * 64;      // pixel base within the row
    const int pbase = h * WW + w0;

    // ---- param phase: thread computes pixel pp = tid>>3 (8x redundant) ----
    {
        const int pp = tid >> 3;         // 0..63
        const int w  = w0 + pp;
        const int p  = pbase + pp;

        const float fx = __ldg(flow + p);
        const float fy = __ldg(flow + HW + p);

        const float x = (float)w + fx;
        const float y = (float)h + fy;

        const float x0f = floorf(x);
        const float y0f = floorf(y);
        const int x0 = (int)x0f;
        const int y0 = (int)y0f;
        const int x1 = x0 + 1;
        const int y1 = y0 + 1;

        const float wx1 = x - x0f;
        const float wx0 = 1.0f - wx1;
        const float wy1 = y - y0f;
        const float wy0 = 1.0f - wy1;

        const bool vx0 = (x0 >= 0) & (x0 <= WW - 1);
        const bool vx1 = (x1 >= 0) & (x1 <= WW - 1);
        const bool vy0 = (y0 >= 0) & (y0 <= HH - 1);
        const bool vy1 = (y1 >= 0) & (y1 <= HH - 1);

        const float w00 = (vy0 & vx0) ? wy0 * wx0 : 0.0f;
        const float w01 = (vy0 & vx1) ? wy0 * wx1 : 0.0f;
        const float w10 = (vy1 & vx0) ? wy1 * wx0 : 0.0f;
        const float w11 = (vy1 & vx1) ? wy1 * wx1 : 0.0f;

        uint4 wh;
        wh.x = h2_bits(__half2half2(__float2half_rn(w00)));
        wh.y = h2_bits(__half2half2(__float2half_rn(w01)));
        wh.z = h2_bits(__half2half2(__float2half_rn(w10)));
        wh.w = h2_bits(__half2half2(__float2half_rn(w11)));

        const int xc0 = min(max(x0, 0), WW - 1);
        const int xc1 = min(max(x1, 0), WW - 1);
        const int yc0 = min(max(y0, 0), HH - 1);
        const int yc1 = min(max(y1, 0), HH - 1);

        int4 off;   // uint2 index of the pixel's 64-ch fp16 block (16 uint2/px)
        off.x = (yc0 * WW + xc0) * 16;
        off.y = (yc0 * WW + xc1) * 16;
        off.z = (yc1 * WW + xc0) * 16;
        off.w = (yc1 * WW + xc1) * 16;

        if ((tid & 7) == 0) {
            s_wh[pp] = wh;
            s_o[pp]  = off;
        }
    }
    __syncthreads();

    const int pxlA = tid >> 4;       // 0..31
    const int pxlB = pxlA + 32;      // 32..63
    const int t    = tid & 15;       // channel quad

    const uint4 whA  = s_wh[pxlA];
    const int4  offA = s_o[pxlA];
    const uint4 whB  = s_wh[pxlB];
    const int4  offB = s_o[pxlB];

    const uint2* __restrict__ s8 = (const uint2*)g_nhwc;
    // 8 independent LDG.64 issued before any consumption
    const uint2 a00 = __ldg(s8 + offA.x + t);
    const uint2 a01 = __ldg(s8 + offA.y + t);
    const uint2 a10 = __ldg(s8 + offA.z + t);
    const uint2 a11 = __ldg(s8 + offA.w + t);
    const uint2 b00 = __ldg(s8 + offB.x + t);
    const uint2 b01 = __ldg(s8 + offB.y + t);
    const uint2 b10 = __ldg(s8 + offB.z + t);
    const uint2 b11 = __ldg(s8 + offB.w + t);

    // fp16 4-tap reduce: channels (c0,c0+1) in *.x, (c0+2,c0+3) in *.y
    __half2 accA01 = __hmul2(bits_h2(whA.x), bits_h2(a00.x));
    accA01 = __hfma2(bits_h2(whA.y), bits_h2(a01.x), accA01);
    accA01 = __hfma2(bits_h2(whA.z), bits_h2(a10.x), accA01);
    accA01 = __hfma2(bits_h2(whA.w), bits_h2(a11.x), accA01);
    __half2 accA23 = __hmul2(bits_h2(whA.x), bits_h2(a00.y));
    accA23 = __hfma2(bits_h2(whA.y), bits_h2(a01.y), accA23);
    accA23 = __hfma2(bits_h2(whA.z), bits_h2(a10.y), accA23);
    accA23 = __hfma2(bits_h2(whA.w), bits_h2(a11.y), accA23);
    __half2 accB01 = __hmul2(bits_h2(whB.x), bits_h2(b00.x));
    accB01 = __hfma2(bits_h2(whB.y), bits_h2(b01.x), accB01);
    accB01 = __hfma2(bits_h2(whB.z), bits_h2(b10.x), accB01);
    accB01 = __hfma2(bits_h2(whB.w), bits_h2(b11.x), accB01);
    __half2 accB23 = __hmul2(bits_h2(whB.x), bits_h2(b00.y));
    accB23 = __hfma2(bits_h2(whB.y), bits_h2(b01.y), accB23);
    accB23 = __hfma2(bits_h2(whB.z), bits_h2(b10.y), accB23);
    accB23 = __hfma2(bits_h2(whB.w), bits_h2(b11.y), accB23);

    const float2 fA01 = __half22float2(accA01);
    const float2 fA23 = __half22float2(accA23);
    const float2 fB01 = __half22float2(accB01);
    const float2 fB23 = __half22float2(accB23);

    const int c0 = 4 * t;
    s2[S2IDX(c0 + 0, pxlA)] = fA01.x;
    s2[S2IDX(c0 + 1, pxlA)] = fA01.y;
    s2[S2IDX(c0 + 2, pxlA)] = fA23.x;
    s2[S2IDX(c0 + 3, pxlA)] = fA23.y;
    s2[S2IDX(c0 + 0, pxlB)] = fB01.x;
    s2[S2IDX(c0 + 1, pxlB)] = fB01.y;
    s2[S2IDX(c0 + 2, pxlB)] = fB23.x;
    s2[S2IDX(c0 + 3, pxlB)] = fB23.y;
    __syncthreads();

    // 4096 floats = 1024 float4: 2 iters x 512 threads.
    // Per channel, 16 lanes store 16 float4 = 256B contiguous. __stcs:
    // output never re-read; don't evict the scratch.
    float4* __restrict__ out4 = (float4*)out;
    #pragma unroll
    for (int k = 0; k < 2; k++) {
        const int idx = tid + 512 * k;
        const int c  = idx >> 4;         // 0..63
        const int j4 = idx & 15;         // float4 column
        const float4 v = *(const float4*)&s2[c * 64 + (((4 * j4) ^ ((c >> 2) << 2)) & 63)];
        __stcs(out4 + (size_t)c * (HW / 4) + (pbase >> 2) + j4, v);
    }
}

extern "C" void kernel_launch(void* const* d_in, const int* in_sizes, int n_in,
                              void* d_out, int out_size)
{
    const float* input1 = (const float*)d_in[0];  // [8,64,256,448] fp32
    const float* input2 = (const float*)d_in[1];  // [8,2,256,448] fp32
    float* out = (float*)d_out;

    const int TBLOCKS = HW / 64;       // 1792
    dim3 ggrid(WW / 64, HH);           // (7, 256) = 1792 blocks

    for (int b = 0; b < BB; b++) {
        transpose_kernel<<<TBLOCKS, 256>>>(input1 + (size_t)b * CHW);
        warp_gather_kernel<<<ggrid, 512>>>(input2 + (size_t)b * 2 * HW,
                                           out + (size_t)b * CHW);
    }
}